// round 7
// baseline (speedup 1.0000x reference)
#include <cuda_runtime.h>

// 16k -> 24k polyphase resampler (torchaudio/kaldi defaults).
// in_unit=2, out_unit=3 phases, first_indices={-6,-5,-4}, W=13 taps.
// out[c, n] = sum_j x[c, (n%3 - 6) + 2*(n/3) + j] * w[n%3][j], zero-padded x.
//
// Warp-halo scheme: thread t owns input floats [8t, 8t+8) via two coalesced
// LDG.128; 8-float halos come from lanes l+-1 via SHFL (off the L1tex pipe).
// Edge lanes issue their halo loads up-front (MLP). Weights in __constant__.
// 12 outputs/thread, quad-interleaved vector stores. occ target 87.5%.

#define C_CH    8
#define NPHASE  3
#define WTAPS   13
#define OUT_PT  12   // outputs per thread (4 units x 3 phases)
#define BLK     256

__constant__ float cw[NPHASE * WTAPS];

__global__ __launch_bounds__(BLK, 7) void resample_16_24_kernel(
    const float* __restrict__ x, float* __restrict__ out, int L, int tot)
{
    const int c = blockIdx.y;
    const int t = blockIdx.x * BLK + threadIdx.x;
    const int n0 = t * OUT_PT;
    if (n0 >= tot) return;          // whole warps exit (500000 = 15625 full warps)

    const int lane = threadIdx.x & 31;
    const float* xc = x + (size_t)c * (size_t)L;
    const int g0 = 8 * t;           // own floats [g0, g0+8); g0+8 <= L always

    const float4* p = reinterpret_cast<const float4*>(xc + g0);

    // Front-load ALL global reads (own data + edge halos) for max MLP.
    float4 A = __ldg(&p[0]);
    float4 B = __ldg(&p[1]);

    const bool lft = (lane == 0);
    const bool rgt = (lane == 31);
    float4 PA, PB, NA, NB;
    bool lv = false, rv = false;
    if (lft && g0 - 8 >= 0)  { PA = __ldg(&p[-2]); PB = __ldg(&p[-1]); lv = true; }
    if (rgt && g0 + 16 <= L) { NA = __ldg(&p[2]);  NB = __ldg(&p[3]);  rv = true; }

    // xin covers [8t-8, 8t+16); taps only use xin[2..22].
    float xin[24];
    const unsigned m = 0xffffffffu;
    xin[2]  = __shfl_up_sync(m, A.z, 1);
    xin[3]  = __shfl_up_sync(m, A.w, 1);
    xin[4]  = __shfl_up_sync(m, B.x, 1);
    xin[5]  = __shfl_up_sync(m, B.y, 1);
    xin[6]  = __shfl_up_sync(m, B.z, 1);
    xin[7]  = __shfl_up_sync(m, B.w, 1);
    xin[8]  = A.x; xin[9]  = A.y; xin[10] = A.z; xin[11] = A.w;
    xin[12] = B.x; xin[13] = B.y; xin[14] = B.z; xin[15] = B.w;
    xin[16] = __shfl_down_sync(m, A.x, 1);
    xin[17] = __shfl_down_sync(m, A.y, 1);
    xin[18] = __shfl_down_sync(m, A.z, 1);
    xin[19] = __shfl_down_sync(m, A.w, 1);
    xin[20] = __shfl_down_sync(m, B.x, 1);
    xin[21] = __shfl_down_sync(m, B.y, 1);
    xin[22] = __shfl_down_sync(m, B.z, 1);

    // Patch warp-edge halos.
    if (lft) {
        if (lv) {
            xin[2] = PA.z; xin[3] = PA.w;
            xin[4] = PB.x; xin[5] = PB.y; xin[6] = PB.z; xin[7] = PB.w;
        } else {
            // channel start: g0 == 0, indices g0-6..g0-1 are zero padding
#pragma unroll
            for (int q = 2; q < 8; q++) {
                int g = g0 - 8 + q;
                xin[q] = (g >= 0) ? xc[g] : 0.0f;
            }
        }
    }
    if (rgt) {
        if (rv) {
            xin[16] = NA.x; xin[17] = NA.y; xin[18] = NA.z; xin[19] = NA.w;
            xin[20] = NB.x; xin[21] = NB.y; xin[22] = NB.z;
        } else {
            // channel end: zero padding past L
#pragma unroll
            for (int q = 0; q < 7; q++) {
                int g = g0 + 8 + q;
                xin[16 + q] = (g < L) ? xc[g] : 0.0f;
            }
        }
    }

    // 12 outputs: n = n0 + 3u + i reads xin[(2+i+2u) .. +12]; weights from
    // constant bank. Compute quad-by-quad, store immediately (low liveness).
    float* oc = out + (size_t)c * (size_t)tot + n0;
    float4* po = reinterpret_cast<float4*>(oc);
#pragma unroll
    for (int q = 0; q < 3; q++) {
        float o4[4];
#pragma unroll
        for (int r = 0; r < 4; r++) {
            const int n = 4 * q + r;
            const int u = n / 3;
            const int i = n % 3;
            const int base = 2 + i + 2 * u;
            float s = 0.0f;
#pragma unroll
            for (int j = 0; j < WTAPS; j++)
                s = fmaf(xin[base + j], cw[i * WTAPS + j], s);
            o4[r] = s;
        }
        po[q] = make_float4(o4[0], o4[1], o4[2], o4[3]);
    }
}

extern "C" void kernel_launch(void* const* d_in, const int* in_sizes, int n_in,
                              void* d_out, int out_size)
{
    const float* x   = (const float*)d_in[0];
    const float* wgt = (const float*)d_in[1];
    float* out = (float*)d_out;

    const int L   = in_sizes[0] / C_CH;   // 4,000,000
    const int tot = out_size   / C_CH;    // 6,000,000 (divisible by 12)

    // Stage filter bank into constant memory (DtoD, on captured legacy stream)
    cudaMemcpyToSymbolAsync(cw, wgt, NPHASE * WTAPS * sizeof(float), 0,
                            cudaMemcpyDeviceToDevice, 0);

    const int threads_per_ch = (tot + OUT_PT - 1) / OUT_PT;
    const int bx = (threads_per_ch + BLK - 1) / BLK;
    dim3 grid(bx, C_CH);
    resample_16_24_kernel<<<grid, BLK>>>(x, out, L, tot);
}

// round 8
// speedup vs baseline: 1.5044x; 1.5044x over previous
#include <cuda_runtime.h>

// 16k -> 24k polyphase resampler (torchaudio/kaldi defaults).
// in_unit=2, out_unit=3 phases, first_indices={-6,-5,-4}, W=13 taps.
// out[c, n] = sum_j x[c, (n%3 - 6) + 2*(n/3) + j] * w[n%3][j], zero-padded x.
//
// Warp-halo scheme (R5 config, 40-reg budget — caps below ~40 spill to local
// and regress): thread t owns input floats [8t, 8t+8) via two coalesced
// LDG.128; 8-float halos come from lanes l+-1 via SHFL (off the L1tex pipe).
// Edge lanes issue their halo loads up-front (MLP). Weights in __constant__.
// 12 outputs/thread, quad-interleaved vector stores.

#define C_CH    8
#define NPHASE  3
#define WTAPS   13
#define OUT_PT  12   // outputs per thread (4 units x 3 phases)
#define BLK     256

__constant__ float cw[NPHASE * WTAPS];

__global__ __launch_bounds__(BLK, 6) void resample_16_24_kernel(
    const float* __restrict__ x, float* __restrict__ out, int L, int tot)
{
    const int c = blockIdx.y;
    const int t = blockIdx.x * BLK + threadIdx.x;
    const int n0 = t * OUT_PT;
    if (n0 >= tot) return;          // whole warps exit (500000 = 15625 full warps)

    const int lane = threadIdx.x & 31;
    const float* xc = x + (size_t)c * (size_t)L;
    const int g0 = 8 * t;           // own floats [g0, g0+8); g0+8 <= L always

    const float4* p = reinterpret_cast<const float4*>(xc + g0);

    // Front-load ALL global reads (own data + edge halos) for max MLP.
    float4 A = __ldg(&p[0]);
    float4 B = __ldg(&p[1]);

    const bool lft = (lane == 0);
    const bool rgt = (lane == 31);
    float4 PA, PB, NA, NB;
    bool lv = false, rv = false;
    if (lft && g0 - 8 >= 0)  { PA = __ldg(&p[-2]); PB = __ldg(&p[-1]); lv = true; }
    if (rgt && g0 + 16 <= L) { NA = __ldg(&p[2]);  NB = __ldg(&p[3]);  rv = true; }

    // xin covers [8t-8, 8t+16); taps only use xin[2..22].
    float xin[24];
    const unsigned m = 0xffffffffu;
    xin[2]  = __shfl_up_sync(m, A.z, 1);
    xin[3]  = __shfl_up_sync(m, A.w, 1);
    xin[4]  = __shfl_up_sync(m, B.x, 1);
    xin[5]  = __shfl_up_sync(m, B.y, 1);
    xin[6]  = __shfl_up_sync(m, B.z, 1);
    xin[7]  = __shfl_up_sync(m, B.w, 1);
    xin[8]  = A.x; xin[9]  = A.y; xin[10] = A.z; xin[11] = A.w;
    xin[12] = B.x; xin[13] = B.y; xin[14] = B.z; xin[15] = B.w;
    xin[16] = __shfl_down_sync(m, A.x, 1);
    xin[17] = __shfl_down_sync(m, A.y, 1);
    xin[18] = __shfl_down_sync(m, A.z, 1);
    xin[19] = __shfl_down_sync(m, A.w, 1);
    xin[20] = __shfl_down_sync(m, B.x, 1);
    xin[21] = __shfl_down_sync(m, B.y, 1);
    xin[22] = __shfl_down_sync(m, B.z, 1);

    // Patch warp-edge halos.
    if (lft) {
        if (lv) {
            xin[2] = PA.z; xin[3] = PA.w;
            xin[4] = PB.x; xin[5] = PB.y; xin[6] = PB.z; xin[7] = PB.w;
        } else {
            // channel start: g0 == 0, indices g0-6..g0-1 are zero padding
#pragma unroll
            for (int q = 2; q < 8; q++) {
                int g = g0 - 8 + q;
                xin[q] = (g >= 0) ? xc[g] : 0.0f;
            }
        }
    }
    if (rgt) {
        if (rv) {
            xin[16] = NA.x; xin[17] = NA.y; xin[18] = NA.z; xin[19] = NA.w;
            xin[20] = NB.x; xin[21] = NB.y; xin[22] = NB.z;
        } else {
            // channel end: zero padding past L
#pragma unroll
            for (int q = 0; q < 7; q++) {
                int g = g0 + 8 + q;
                xin[16 + q] = (g < L) ? xc[g] : 0.0f;
            }
        }
    }

    // 12 outputs: n = n0 + 3u + i reads xin[(2+i+2u) .. +12]; weights from
    // constant bank. Compute quad-by-quad, store immediately (low liveness).
    float* oc = out + (size_t)c * (size_t)tot + n0;
    float4* po = reinterpret_cast<float4*>(oc);
#pragma unroll
    for (int q = 0; q < 3; q++) {
        float o4[4];
#pragma unroll
        for (int r = 0; r < 4; r++) {
            const int n = 4 * q + r;
            const int u = n / 3;
            const int i = n % 3;
            const int base = 2 + i + 2 * u;
            float s = 0.0f;
#pragma unroll
            for (int j = 0; j < WTAPS; j++)
                s = fmaf(xin[base + j], cw[i * WTAPS + j], s);
            o4[r] = s;
        }
        po[q] = make_float4(o4[0], o4[1], o4[2], o4[3]);
    }
}

extern "C" void kernel_launch(void* const* d_in, const int* in_sizes, int n_in,
                              void* d_out, int out_size)
{
    const float* x   = (const float*)d_in[0];
    const float* wgt = (const float*)d_in[1];
    float* out = (float*)d_out;

    const int L   = in_sizes[0] / C_CH;   // 4,000,000
    const int tot = out_size   / C_CH;    // 6,000,000 (divisible by 12)

    // Stage filter bank into constant memory (DtoD, on captured legacy stream)
    cudaMemcpyToSymbolAsync(cw, wgt, NPHASE * WTAPS * sizeof(float), 0,
                            cudaMemcpyDeviceToDevice, 0);

    const int threads_per_ch = (tot + OUT_PT - 1) / OUT_PT;
    const int bx = (threads_per_ch + BLK - 1) / BLK;
    dim3 grid(bx, C_CH);
    resample_16_24_kernel<<<grid, BLK>>>(x, out, L, tot);
}

// round 9
// speedup vs baseline: 1.6114x; 1.0711x over previous
#include <cuda_runtime.h>

// 16k -> 24k polyphase resampler (torchaudio/kaldi defaults).
// in_unit=2, out_unit=3 phases, first_indices={-6,-5,-4}, W=13 taps.
// out[c, n] = sum_j x[c, (n%3 - 6) + 2*(n/3) + j] * w[n%3][j], zero-padded x.
//
// R5 structure (known-good 55.8us): thread t owns input floats [8t, 8t+8) via
// two coalesced LDG.128; halos from lanes l+-1 via SHFL; edge-lane patch AFTER
// the shuffle chain (placing it before inserts divergence into the shfl
// critical path — R8 regression). Weights in __constant__. Streaming cache
// hints (.cs) on the touch-once load/store streams. 40-reg budget; caps below
// ~40 spill to local and regress (R7).

#define C_CH    8
#define NPHASE  3
#define WTAPS   13
#define OUT_PT  12   // outputs per thread (4 units x 3 phases)
#define BLK     256

__constant__ float cw[NPHASE * WTAPS];

__global__ __launch_bounds__(BLK, 6) void resample_16_24_kernel(
    const float* __restrict__ x, float* __restrict__ out, int L, int tot)
{
    const int c = blockIdx.y;
    const int t = blockIdx.x * BLK + threadIdx.x;
    const int n0 = t * OUT_PT;
    if (n0 >= tot) return;          // whole warps exit (500000 = 15625 full warps)

    const int lane = threadIdx.x & 31;
    const float* xc = x + (size_t)c * (size_t)L;
    const int g0 = 8 * t;           // own floats [g0, g0+8); g0+8 <= L always

    // Own data: 2 coalesced vector loads, streaming (touch-once) hint.
    const float4* p = reinterpret_cast<const float4*>(xc + g0);
    float4 A = __ldcs(&p[0]);
    float4 B = __ldcs(&p[1]);

    // xin covers [8t-8, 8t+16); taps only use xin[2..22].
    float xin[24];
    const unsigned m = 0xffffffffu;
    xin[2]  = __shfl_up_sync(m, A.z, 1);
    xin[3]  = __shfl_up_sync(m, A.w, 1);
    xin[4]  = __shfl_up_sync(m, B.x, 1);
    xin[5]  = __shfl_up_sync(m, B.y, 1);
    xin[6]  = __shfl_up_sync(m, B.z, 1);
    xin[7]  = __shfl_up_sync(m, B.w, 1);
    xin[8]  = A.x; xin[9]  = A.y; xin[10] = A.z; xin[11] = A.w;
    xin[12] = B.x; xin[13] = B.y; xin[14] = B.z; xin[15] = B.w;
    xin[16] = __shfl_down_sync(m, A.x, 1);
    xin[17] = __shfl_down_sync(m, A.y, 1);
    xin[18] = __shfl_down_sync(m, A.z, 1);
    xin[19] = __shfl_down_sync(m, A.w, 1);
    xin[20] = __shfl_down_sync(m, B.x, 1);
    xin[21] = __shfl_down_sync(m, B.y, 1);
    xin[22] = __shfl_down_sync(m, B.z, 1);

    // Warp-edge lanes fetch their halo directly (after the shuffle chain;
    // rare guarded scalar path only at channel edges).
    if (lane == 0) {
        const int gl = g0 - 8;
        if (gl >= 0) {
            float4 PA = __ldg(&p[-2]);
            float4 PB = __ldg(&p[-1]);
            xin[2] = PA.z; xin[3] = PA.w;
            xin[4] = PB.x; xin[5] = PB.y; xin[6] = PB.z; xin[7] = PB.w;
        } else {
#pragma unroll
            for (int q = 2; q < 8; q++) {
                int g = gl + q;
                xin[q] = (g >= 0) ? xc[g] : 0.0f;
            }
        }
    }
    if (lane == 31) {
        const int gr = g0 + 8;
        if (gr + 8 <= L) {
            float4 NA = __ldg(&p[2]);
            float4 NB = __ldg(&p[3]);
            xin[16] = NA.x; xin[17] = NA.y; xin[18] = NA.z; xin[19] = NA.w;
            xin[20] = NB.x; xin[21] = NB.y; xin[22] = NB.z;
        } else {
#pragma unroll
            for (int q = 0; q < 7; q++) {
                int g = gr + q;
                xin[16 + q] = (g < L) ? xc[g] : 0.0f;
            }
        }
    }

    // 12 outputs: n = n0 + 3u + i reads xin[(2+i+2u) .. +12]; weights from
    // constant bank. Compute quad-by-quad, store immediately (low liveness).
    // Streaming store hint: output is never re-read.
    float* oc = out + (size_t)c * (size_t)tot + n0;
    float4* po = reinterpret_cast<float4*>(oc);
#pragma unroll
    for (int q = 0; q < 3; q++) {
        float o4[4];
#pragma unroll
        for (int r = 0; r < 4; r++) {
            const int n = 4 * q + r;
            const int u = n / 3;
            const int i = n % 3;
            const int base = 2 + i + 2 * u;
            float s = 0.0f;
#pragma unroll
            for (int j = 0; j < WTAPS; j++)
                s = fmaf(xin[base + j], cw[i * WTAPS + j], s);
            o4[r] = s;
        }
        __stcs(&po[q], make_float4(o4[0], o4[1], o4[2], o4[3]));
    }
}

extern "C" void kernel_launch(void* const* d_in, const int* in_sizes, int n_in,
                              void* d_out, int out_size)
{
    const float* x   = (const float*)d_in[0];
    const float* wgt = (const float*)d_in[1];
    float* out = (float*)d_out;

    const int L   = in_sizes[0] / C_CH;   // 4,000,000
    const int tot = out_size   / C_CH;    // 6,000,000 (divisible by 12)

    // Stage filter bank into constant memory (DtoD, on captured legacy stream)
    cudaMemcpyToSymbolAsync(cw, wgt, NPHASE * WTAPS * sizeof(float), 0,
                            cudaMemcpyDeviceToDevice, 0);

    const int threads_per_ch = (tot + OUT_PT - 1) / OUT_PT;
    const int bx = (threads_per_ch + BLK - 1) / BLK;
    dim3 grid(bx, C_CH);
    resample_16_24_kernel<<<grid, BLK>>>(x, out, L, tot);
}